// round 6
// baseline (speedup 1.0000x reference)
#include <cuda_runtime.h>
#include <math.h>
#include <stdint.h>

#define BB 32
#define TT 512
#define EE 256
#define UU 512
#define U3 1536
#define NBLK 64          // blocks per direction in recurrence
#define RGRID (2*NBLK)   // total recurrence blocks
#define PADK 516         // padded k-stride for h rows (conflict-free LDS.32)
#define PK2  521         // float2 stride for U hi/lo (conflict-free LDS.64)
#define PSC  289         // psum col stride (floats)
#define PSB  9           // psum row stride (8 slots + pad)

// ---------------- device scratch (static; no runtime allocation) ------------
__device__ float    g_xproj[2][BB][TT][U3];   // x@W + b_in per direction
__device__ float    g_h[2][2][BB][UU];        // [dir][buf][b][u] double-buffered state
__device__ unsigned g_cnt[2][TT];             // per-step barrier counters (memset to 0)

// ---------------- packed f32x2 helpers (xproj kernel) -----------------------
__device__ __forceinline__ unsigned long long ffma2(unsigned long long a,
                                                    unsigned long long b,
                                                    unsigned long long c) {
    unsigned long long d;
    asm("fma.rn.f32x2 %0, %1, %2, %3;" : "=l"(d) : "l"(a), "l"(b), "l"(c));
    return d;
}
__device__ __forceinline__ unsigned long long dup2(float x) {
    unsigned long long d;
    asm("mov.b64 %0, {%1, %1};" : "=l"(d) : "f"(x));
    return d;
}
__device__ __forceinline__ float2 unpack2(unsigned long long v) {
    float2 r;
    asm("mov.b64 {%0, %1}, %2;" : "=f"(r.x), "=f"(r.y) : "l"(v));
    return r;
}

// ---------------- tf32 mma helper -------------------------------------------
__device__ __forceinline__ void mma_tf32(float& d0, float& d1, float& d2, float& d3,
                                         unsigned a0, unsigned a1, unsigned a2, unsigned a3,
                                         unsigned b0, unsigned b1) {
    asm volatile(
        "mma.sync.aligned.m16n8k8.row.col.f32.tf32.tf32.f32 "
        "{%0,%1,%2,%3}, {%4,%5,%6,%7}, {%8,%9}, {%0,%1,%2,%3};"
        : "+f"(d0), "+f"(d1), "+f"(d2), "+f"(d3)
        : "r"(a0), "r"(a1), "r"(a2), "r"(a3), "r"(b0), "r"(b1));
}
__device__ __forceinline__ unsigned tf32_hi_bits(float x) {
    return __float_as_uint(x) & 0xFFFFE000u;
}

// ---------------- Kernel A: x_proj = emb[tokens] @ W + b_in -----------------
#define BM 128
#define BN 64
#define BK 16

__global__ void __launch_bounds__(256) xproj_kernel(
    const int* __restrict__ tokens,
    const float* __restrict__ emb,
    const float* __restrict__ W_fw, const float* __restrict__ b_in_fw,
    const float* __restrict__ W_bw, const float* __restrict__ b_in_bw)
{
    __shared__ __align__(16) float As[BK][BM];
    __shared__ __align__(16) float Bs[BK][BN];
    __shared__ int toks[BM];

    const int d  = blockIdx.z;
    const float* __restrict__ Wp = d ? W_bw : W_fw;
    const float* __restrict__ bp = d ? b_in_bw : b_in_fw;
    const int n0 = blockIdx.x * BN;
    const int m0 = blockIdx.y * BM;
    const int tid = threadIdx.x;
    const int tx = tid & 15;
    const int ty = tid >> 4;

    if (tid < BM) toks[tid] = tokens[m0 + tid];
    __syncthreads();

    unsigned long long acc[4][4];
#pragma unroll
    for (int i = 0; i < 4; i++)
#pragma unroll
        for (int j = 0; j < 4; j++) acc[i][j] = 0ull;

    for (int k0 = 0; k0 < EE; k0 += BK) {
#pragma unroll
        for (int i = 0; i < 2; i++) {
            int id = tid * 2 + i;
            int m  = id >> 2;
            int kg = id & 3;
            float4 v = *(const float4*)(emb + (size_t)toks[m] * EE + k0 + kg * 4);
            As[kg*4+0][m] = v.x; As[kg*4+1][m] = v.y;
            As[kg*4+2][m] = v.z; As[kg*4+3][m] = v.w;
        }
        {
            int k = tid >> 4, ng = tid & 15;
            *(float4*)&Bs[k][ng*4] =
                *(const float4*)(Wp + (size_t)(k0 + k) * U3 + n0 + ng * 4);
        }
        __syncthreads();
#pragma unroll
        for (int k = 0; k < BK; k++) {
            ulonglong2 a01 = *(const ulonglong2*)&As[k][ty*8];
            ulonglong2 a23 = *(const ulonglong2*)&As[k][ty*8+4];
            float4 b4 = *(const float4*)&Bs[k][tx*4];
            unsigned long long ap[4] = {a01.x, a01.y, a23.x, a23.y};
            unsigned long long bp2[4] = {dup2(b4.x), dup2(b4.y), dup2(b4.z), dup2(b4.w)};
#pragma unroll
            for (int i = 0; i < 4; i++)
#pragma unroll
                for (int j = 0; j < 4; j++)
                    acc[i][j] = ffma2(ap[i], bp2[j], acc[i][j]);
        }
        __syncthreads();
    }

    float4 bias = *(const float4*)(bp + n0 + tx * 4);
    float* gx = &g_xproj[0][0][0][0];
#pragma unroll
    for (int i = 0; i < 4; i++) {
        float2 c0 = unpack2(acc[i][0]);
        float2 c1 = unpack2(acc[i][1]);
        float2 c2 = unpack2(acc[i][2]);
        float2 c3 = unpack2(acc[i][3]);
        size_t mlo = (size_t)(m0 + ty * 8 + i * 2);
        float4 vlo = { c0.x + bias.x, c1.x + bias.y, c2.x + bias.z, c3.x + bias.w };
        float4 vhi = { c0.y + bias.x, c1.y + bias.y, c2.y + bias.z, c3.y + bias.w };
        *(float4*)(gx + ((size_t)d * (BB*TT) + mlo)     * U3 + n0 + tx * 4) = vlo;
        *(float4*)(gx + ((size_t)d * (BB*TT) + mlo + 1) * U3 + n0 + tx * 4) = vhi;
    }
}

// ---------------- Kernel B: persistent GRU recurrence (tf32 tensor cores) ---
// 128 blocks (64/dir), 512 threads = 16 warps = (2 m-tiles x 8 k-splits).
// P[32x24] = H[32x512] * U[512x24] via m16n8k8.tf32, 2-way split,
// 9 independent accumulator sets (3 n-tiles x 3 products) -> short mma chains.
// U hi/lo interleaved float2 in SMEM; psum [24][32][9]; mask bitmap in SMEM.
#define GRU_SMEM_FLOATS (32*PADK + 2*24*PK2 + 24*PSC + 32 + 32*16/2*0 + 512)
#define SMEM_BYTES ((32*PADK + 2*24*PK2 + 24*PSC + 64) * 4 + 512*4)

__global__ void __launch_bounds__(512, 1) gru_kernel(
    const int* __restrict__ tokens,
    const float* __restrict__ U_fw, const float* __restrict__ b_rec_fw,
    const float* __restrict__ U_bw, const float* __restrict__ b_rec_bw,
    float* __restrict__ out)
{
    extern __shared__ float smem[];
    float*  hs   = smem;                         // [32][516] h (fp32)
    float2* UsP  = (float2*)(hs + 32*PADK);      // [24][521] {hi, lo}
    float*  psum = (float*)(UsP + 24*PK2);       // [24][32][9] (strides 289/9)
    unsigned* maskw = (unsigned*)(psum + 24*PSC + 64);  // [32][16] mask bits

    const int bid = blockIdx.x;
    const int d   = bid >> 6;
    const int jb  = bid & (NBLK - 1);
    const int u0  = jb * 8;
    const int tid = threadIdx.x;
    const int wid = tid >> 5;
    const int lane = tid & 31;
    const int mi = wid & 1;          // m-tile (rows mi*16 .. +15)
    const int kh = wid >> 1;         // k-split 0..7 (range kh*64 .. +64)
    const int gr = lane >> 2;        // fragment group row
    const int gc = lane & 3;         // fragment group col

    const float* __restrict__ Uw = d ? U_bw : U_fw;
    const float* __restrict__ br = d ? b_rec_bw : b_rec_fw;

    // stage U hi/lo once (reused all 512 steps)
    for (int idx = tid; idx < 24 * 512; idx += 512) {
        int c = idx >> 9;            // col 0..23 (c = g*8 + ul)
        int k = idx & 511;
        int g = c >> 3;
        float v = Uw[(size_t)k * U3 + g * 512 + u0 + (c & 7)];
        float hi = __uint_as_float(tf32_hi_bits(v));
        UsP[c * PK2 + k] = make_float2(hi, v - hi);
    }
    // mask bitmap: maskw[b][w] bit i = (tokens[b, w*32+i] != 0)
    {
        int b = tid >> 4, w = tid & 15;
        unsigned m = 0;
        const int* tp = tokens + b * TT + w * 32;
#pragma unroll 8
        for (int i = 0; i < 32; i++) m |= (tp[i] != 0 ? (1u << i) : 0u);
        maskw[b * 16 + w] = m;
    }

    // epilogue mapping (threads 0..255): batch eb, unit eu
    const int eb = tid >> 3, eu = tid & 7;
    float brz = 0.f, brr = 0.f, brh = 0.f;
    if (tid < 256) {
        brz = br[0*512 + u0 + eu];
        brr = br[1*512 + u0 + eu];
        brh = br[2*512 + u0 + eu];
    }

    const float* gx = &g_xproj[0][0][0][0];

    const int rA0 = (mi*16 + gr) * PADK + gc;   // A frag rows gr / gr+8
    const int rA1 = rA0 + 8 * PADK;
    const int r0  = mi*16 + gr;
    const int r1  = r0 + 8;
    const int kbase = kh * 64;

    __syncthreads();

    for (int ts = 0; ts < TT; ts++) {
        const int t   = d ? (TT - 1 - ts) : ts;
        const int buf = ts & 1;

        // stage h_prev into padded SMEM rows (8 float4 per thread)
        const float4* hp_g = (const float4*)&g_h[d][buf][0][0];
#pragma unroll
        for (int i = 0; i < 8; i++) {
            int id  = tid + i * 512;       // 0..4095 float4 slots
            int row = id >> 7;
            int q   = id & 127;
            *(float4*)&hs[row * PADK + q * 4] = hp_g[id];
        }
        // prefetch epilogue inputs (latency hidden under sync + dot)
        float xz = 0.f, xr = 0.f, xh = 0.f;
        if (tid < 256) {
            size_t xb = ((size_t)d * (BB*TT) + (size_t)eb * TT + t) * U3;
            xz = gx[xb + u0 + eu];
            xr = gx[xb + 512 + u0 + eu];
            xh = gx[xb + 1024 + u0 + eu];
        }
        __syncthreads();

        // ---- tensor-core dot: 8 k-tiles, 3 n-tiles, 9 independent acc sets
        float Dhh[3][4], Dhl[3][4], Dlh[3][4];
#pragma unroll
        for (int j = 0; j < 3; j++)
#pragma unroll
            for (int q = 0; q < 4; q++) { Dhh[j][q] = 0.f; Dhl[j][q] = 0.f; Dlh[j][q] = 0.f; }

#pragma unroll
        for (int kt = 0; kt < 8; kt++) {
            int k0 = kbase + kt * 8;
            float f0 = hs[rA0 + k0];
            float f1 = hs[rA1 + k0];
            float f2 = hs[rA0 + k0 + 4];
            float f3 = hs[rA1 + k0 + 4];
            unsigned a0h = tf32_hi_bits(f0);
            unsigned a1h = tf32_hi_bits(f1);
            unsigned a2h = tf32_hi_bits(f2);
            unsigned a3h = tf32_hi_bits(f3);
            unsigned a0l = __float_as_uint(f0 - __uint_as_float(a0h));
            unsigned a1l = __float_as_uint(f1 - __uint_as_float(a1h));
            unsigned a2l = __float_as_uint(f2 - __uint_as_float(a2h));
            unsigned a3l = __float_as_uint(f3 - __uint_as_float(a3h));
#pragma unroll
            for (int j = 0; j < 3; j++) {
                const float2* bp2 = UsP + (j*8 + gr) * PK2 + k0 + gc;
                float2 blo = bp2[0];     // {hi, lo} at k0+gc
                float2 bhi = bp2[4];     // {hi, lo} at k0+gc+4
                unsigned b0 = __float_as_uint(blo.x);
                unsigned b1 = __float_as_uint(bhi.x);
                unsigned c0 = __float_as_uint(blo.y);
                unsigned c1 = __float_as_uint(bhi.y);
                mma_tf32(Dhh[j][0], Dhh[j][1], Dhh[j][2], Dhh[j][3],
                         a0h, a1h, a2h, a3h, b0, b1);
                mma_tf32(Dhl[j][0], Dhl[j][1], Dhl[j][2], Dhl[j][3],
                         a0h, a1h, a2h, a3h, c0, c1);
                mma_tf32(Dlh[j][0], Dlh[j][1], Dlh[j][2], Dlh[j][3],
                         a0l, a1l, a2l, a3l, b0, b1);
            }
        }

        // combine splits and publish k-partials
#pragma unroll
        for (int j = 0; j < 3; j++) {
            float d0 = Dhh[j][0] + Dhl[j][0] + Dlh[j][0];
            float d1 = Dhh[j][1] + Dhl[j][1] + Dlh[j][1];
            float d2 = Dhh[j][2] + Dhl[j][2] + Dlh[j][2];
            float d3 = Dhh[j][3] + Dhl[j][3] + Dlh[j][3];
            int c0 = j*8 + gc*2, c1 = c0 + 1;
            psum[c0*PSC + r0*PSB + kh] = d0;
            psum[c1*PSC + r0*PSB + kh] = d1;
            psum[c0*PSC + r1*PSB + kh] = d2;
            psum[c1*PSC + r1*PSB + kh] = d3;
        }
        __syncthreads();

        // ---- epilogue: threads 0..255, each = one (batch, unit) ----
        if (tid < 256) {
            const float* pz = psum + (0*8 + eu)*PSC + eb*PSB;
            const float* pr = psum + (1*8 + eu)*PSC + eb*PSB;
            const float* ph = psum + (2*8 + eu)*PSC + eb*PSB;
            float hz = brz, hr = brr, hh = brh;
#pragma unroll
            for (int s = 0; s < 8; s++) {
                hz += pz[s]; hr += pr[s]; hh += ph[s];
            }
            float z    = 1.f / (1.f + expf(-(xz + hz)));
            float r    = 1.f / (1.f + expf(-(xr + hr)));
            float cand = tanhf(xh + r * hh);
            float hp   = hs[eb * PADK + u0 + eu];
            float hn   = z * hp + (1.f - z) * cand;
            if (!((maskw[eb * 16 + (t >> 5)] >> (t & 31)) & 1u)) hn = hp;

            g_h[d][buf ^ 1][eb][u0 + eu] = hn;
            out[((size_t)eb * TT + t) * (2*UU) + (size_t)d * UU + u0 + eu] = hn;
        }

        // inter-block barrier (per direction, per step); counters pre-zeroed
        if (ts + 1 < TT) {
            __syncthreads();
            if (tid == 0) {
                __threadfence();
                atomicAdd(&g_cnt[d][ts], 1u);
                volatile unsigned* c = &g_cnt[d][ts];
                while (*c < NBLK) { }
                __threadfence();
            }
            __syncthreads();
        }
    }
}

// ---------------- launch ----------------------------------------------------
extern "C" void kernel_launch(void* const* d_in, const int* in_sizes, int n_in,
                              void* d_out, int out_size)
{
    const int*   tokens   = (const int*)  d_in[0];
    const float* emb      = (const float*)d_in[1];
    const float* W_fw     = (const float*)d_in[2];
    const float* U_fw     = (const float*)d_in[3];
    const float* b_in_fw  = (const float*)d_in[4];
    const float* b_rec_fw = (const float*)d_in[5];
    const float* W_bw     = (const float*)d_in[6];
    const float* U_bw     = (const float*)d_in[7];
    const float* b_in_bw  = (const float*)d_in[8];
    const float* b_rec_bw = (const float*)d_in[9];
    float* out = (float*)d_out;

    void* p;
    cudaGetSymbolAddress(&p, g_h);
    cudaMemsetAsync(p, 0, sizeof(g_h));
    cudaGetSymbolAddress(&p, g_cnt);
    cudaMemsetAsync(p, 0, sizeof(g_cnt));

    dim3 gA(U3 / BN, (BB * TT) / BM, 2);
    xproj_kernel<<<gA, 256>>>(tokens, emb, W_fw, b_in_fw, W_bw, b_in_bw);

    cudaFuncSetAttribute(gru_kernel,
                         cudaFuncAttributeMaxDynamicSharedMemorySize, SMEM_BYTES);
    gru_kernel<<<RGRID, 512, SMEM_BYTES>>>(tokens, U_fw, b_rec_fw,
                                           U_bw, b_rec_bw, out);
}